// round 9
// baseline (speedup 1.0000x reference)
#include <cuda_runtime.h>
#include <cstdint>

#define N_BINS 15
#define TILE_ROWS 32
#define TILE_FLOATS (TILE_ROWS * 128)
#define TILE_BYTES  (TILE_FLOATS * 4)     // 16 KB

__device__ float g_sum_conf[N_BINS];
__device__ float g_sum_corr[N_BINS];
__device__ unsigned int g_done_count;

__device__ __forceinline__ unsigned smem_u32(const void* p) {
    unsigned a;
    asm("{ .reg .u64 t; cvta.to.shared.u64 t, %1; cvt.u32.u64 %0, t; }"
        : "=r"(a) : "l"(p));
    return a;
}

#define MBAR_INIT(addr, cnt) \
    asm volatile("mbarrier.init.shared.b64 [%0], %1;" \
                 :: "r"(addr), "r"(cnt) : "memory")

#define MBAR_EXPECT_TX(addr, bytes) \
    asm volatile("mbarrier.arrive.expect_tx.shared.b64 _, [%0], %1;" \
                 :: "r"(addr), "r"(bytes) : "memory")

// 1D bulk async copy global->shared, completion via mbarrier tx-bytes.
#define BULK_G2S(dst, src, bytes, mbar) \
    asm volatile("cp.async.bulk.shared::cluster.global.mbarrier::complete_tx::bytes " \
                 "[%0], [%1], %2, [%3];" \
                 :: "r"(dst), "l"(src), "r"(bytes), "r"(mbar) : "memory")

__device__ __forceinline__ void mbar_wait_parity(unsigned addr, unsigned parity) {
    asm volatile(
        "{\n\t"
        ".reg .pred P;\n\t"
        "WAIT_%=:\n\t"
        "mbarrier.try_wait.parity.acquire.cta.shared::cta.b64 P, [%0], %1, 0x989680;\n\t"
        "@P bra.uni DONE_%=;\n\t"
        "bra.uni WAIT_%=;\n\t"
        "DONE_%=:\n\t"
        "}"
        :: "r"(addr), "r"(parity) : "memory");
}

// Persistent grid (6 blocks/SM by smem: 2x16KB buffers). Each block strides
// over 32-row tiles. Tiles arrive via cp.async.bulk (TMA engine) into a
// double-buffered smem ring -- this bypasses the per-SM LDG/MSHR MLP cap that
// pinned the LDG version at ~6.0 TB/s. Compute reads smem (LDS, short
// latency). Octet layout: 8 threads/row, 4 rows/warp, 32 rows/block-tile.
// No argmax: accuracy == (logits[row][label] == rowmax), xl read from smem.
__global__ __launch_bounds__(256, 6) void ece_main_kernel(
    const float* __restrict__ logits,   // [N,128] fp32
    const int*   __restrict__ labels,   // [N]
    float* __restrict__ out,
    float invN,
    int N,
    unsigned int nblocks)
{
    __shared__ __align__(1024) float buf[2][TILE_FLOATS];
    __shared__ __align__(8) unsigned long long mbar_store[2];
    __shared__ float s_conf[N_BINS];
    __shared__ float s_corr[N_BINS];
    __shared__ bool  s_is_last;

    const int t = threadIdx.x;
    const unsigned mb0 = smem_u32(&mbar_store[0]);
    const unsigned mb1 = smem_u32(&mbar_store[1]);

    if (t < N_BINS) { s_conf[t] = 0.0f; s_corr[t] = 0.0f; }
    if (t == 0) { MBAR_INIT(mb0, 1); MBAR_INIT(mb1, 1); }
    __syncthreads();

    const int lane = t & 31;
    const int warp = t >> 5;
    const int o    = lane & 7;     // position within octet (0..7)
    const int r    = lane >> 3;    // row within warp (0..3)
    const int rowslot = warp * 4 + r;            // 0..31 within tile

    const int n_tiles = (N + TILE_ROWS - 1) / TILE_ROWS;
    const int stride  = (int)gridDim.x;

    // Prologue: issue first tile into buf0.
    const int tile0 = blockIdx.x;
    if (t == 0) {
        int rows0  = min(TILE_ROWS, N - tile0 * TILE_ROWS);
        unsigned b = (unsigned)rows0 * 512u;
        MBAR_EXPECT_TX(mb0, b);
        BULK_G2S(smem_u32(&buf[0][0]),
                 logits + (long long)tile0 * TILE_FLOATS, b, mb0);
    }

    unsigned ph0 = 0, ph1 = 0;
    int i = 0;
    for (int tile = tile0; tile < n_tiles; tile += stride, i++) {
        const int s = i & 1;

        // Issue NEXT tile into the spare buffer (consumed last iteration;
        // the __syncthreads at the end of the previous iteration ordered
        // all reads before this re-fill).
        const int ntile = tile + stride;
        if (t == 0 && ntile < n_tiles) {
            int nrows  = min(TILE_ROWS, N - ntile * TILE_ROWS);
            unsigned b = (unsigned)nrows * 512u;
            unsigned mb  = s ? mb0 : mb1;
            unsigned dst = smem_u32(&buf[1 - s][0]);
            MBAR_EXPECT_TX(mb, b);
            BULK_G2S(dst, logits + (long long)ntile * TILE_FLOATS, b, mb);
        }

        // Prefetch label for this row (LDG latency hides under mbarrier wait).
        const int row  = tile * TILE_ROWS + rowslot;
        const bool lead = (o == 0) && (row < N);
        int lab = 0;
        if (lead) lab = __ldg(labels + row);

        // Wait for current tile.
        if (s == 0) { mbar_wait_parity(mb0, ph0); ph0 ^= 1; }
        else        { mbar_wait_parity(mb1, ph1); ph1 ^= 1; }

        // Compute from smem: thread o of the octet reads float4 chunks
        // {o, o+8, o+16, o+24} of its row (conflict-free LDS.128).
        const float* rp = &buf[s][rowslot * 128];
        float4 v[4];
        #pragma unroll
        for (int k = 0; k < 4; k++)
            v[k] = *(const float4*)(rp + o * 4 + k * 32);

        float ma = fmaxf(fmaxf(v[0].x, v[0].y), fmaxf(v[0].z, v[0].w));
        float mb_ = fmaxf(fmaxf(v[1].x, v[1].y), fmaxf(v[1].z, v[1].w));
        ma = fmaxf(ma,  fmaxf(fmaxf(v[2].x, v[2].y), fmaxf(v[2].z, v[2].w)));
        mb_ = fmaxf(mb_, fmaxf(fmaxf(v[3].x, v[3].y), fmaxf(v[3].z, v[3].w)));
        float m = fmaxf(ma, mb_);

        float sa = 0.0f, sb = 0.0f;
        #pragma unroll
        for (int k = 0; k < 4; k++) {
            sa += __expf(v[k].x) + __expf(v[k].y);
            sb += __expf(v[k].z) + __expf(v[k].w);
        }
        float sm = sa + sb;

        // Octet reductions (3 levels).
        #pragma unroll
        for (int off = 1; off <= 4; off <<= 1) {
            m  = fmaxf(m, __shfl_xor_sync(0xFFFFFFFFu, m, off));
            sm += __shfl_xor_sync(0xFFFFFFFFu, sm, off);
        }

        if (lead) {
            float conf = __expf(m) / sm;          // softmax max prob
            int b = (int)ceilf(conf * (float)N_BINS) - 1;
            b = min(max(b, 0), N_BINS - 1);
            atomicAdd(&s_conf[b], conf);
            float xl = rp[lab];                   // LDS, bit-exact compare
            if (xl == m) atomicAdd(&s_corr[b], 1.0f);
        }

        __syncthreads();   // all reads of buf[s] done before its re-fill
    }

    if (t < N_BINS) {
        atomicAdd(&g_sum_conf[t], s_conf[t]);
        atomicAdd(&g_sum_corr[t], s_corr[t]);
    }
    __syncthreads();

    // Last-block-done: ONE fence per block by ONE thread.
    if (t == 0) {
        __threadfence();
        unsigned int c = atomicAdd(&g_done_count, 1u);
        s_is_last = (c == nblocks - 1);
    }
    __syncthreads();

    if (s_is_last && t == 0) {
        __threadfence();
        float e = 0.0f;
        #pragma unroll
        for (int b = 0; b < N_BINS; b++) {
            e += fabsf(g_sum_conf[b] - g_sum_corr[b]);
            g_sum_conf[b] = 0.0f;
            g_sum_corr[b] = 0.0f;
        }
        out[0] = e * invN;
        g_done_count = 0;
    }
}

extern "C" void kernel_launch(void* const* d_in, const int* in_sizes, int n_in,
                              void* d_out, int out_size)
{
    const float* logits = (const float*)d_in[0];
    const int*   labels = (const int*)d_in[1];
    float*       out    = (float*)d_out;

    const int N = in_sizes[1];   // rows = label count

    // Hint max smem carveout so 6 blocks/SM can co-reside (host-side attr,
    // not captured; idempotent).
    static bool carveout_set = false;
    if (!carveout_set) {
        cudaFuncSetAttribute(ece_main_kernel,
                             cudaFuncAttributePreferredSharedMemoryCarveout, 100);
        carveout_set = true;
    }

    const int n_tiles = (N + TILE_ROWS - 1) / TILE_ROWS;
    unsigned int blocks = 148u * 6u;
    if ((int)blocks > n_tiles) blocks = (unsigned int)n_tiles;

    ece_main_kernel<<<blocks, 256>>>(logits, labels, out,
                                     1.0f / (float)N, N, blocks);
}